// round 10
// baseline (speedup 1.0000x reference)
#include <cuda_runtime.h>
#include <cstdint>

#define N_ANCHOR   900
#define C_DIM      256
#define NUM_CAMS   6
#define NUM_LEVELS 4
#define NUM_PTS    13
#define NUM_FIXED  7
#define NUM_LEARN  6
#define NUM_GROUPS 8
#define NW         2496   // 6*4*13*8
#define NCOMBO     312    // 6*4*13
#define SUM_HW     14960
#define KSPLIT     8

__constant__ int c_lvlW[4]   = {176, 88, 44, 22};
__constant__ int c_lvlH[4]   = {64, 32, 16, 8};
__constant__ int c_start[4]  = {0, 11264, 14080, 14784};

// ---------------- scratch (device globals; no allocation) ----------------
__device__ float  g_X[N_ANCHOR * C_DIM];                      // inst + anchor_embed
__device__ float2 g_pts[N_ANCHOR * NUM_CAMS * NUM_PTS];       // normalized 2D pts
__device__ float  g_W[N_ANCHOR * NW];                         // raw logits (softmax fused into agg)
__device__ float  g_agg[N_ANCHOR * C_DIM];                    // aggregated features
__device__ float  g_part[KSPLIT * N_ANCHOR * C_DIM];          // split-K partials

// ---------------- f32x2 helpers ----------------
__device__ __forceinline__ unsigned long long pk2(float lo, float hi) {
    unsigned long long r;
    asm("mov.b64 %0, {%1, %2};" : "=l"(r) : "f"(lo), "f"(hi));
    return r;
}
__device__ __forceinline__ void upk2(unsigned long long v, float& lo, float& hi) {
    asm("mov.b64 {%0, %1}, %2;" : "=f"(lo), "=f"(hi) : "l"(v));
}
__device__ __forceinline__ void fma2(unsigned long long& d, unsigned long long a, unsigned long long b) {
    asm("fma.rn.f32x2 %0, %1, %2, %0;" : "+l"(d) : "l"(a), "l"(b));
}

// ---------------- kernel 1: embed + keypoints + projection ----------------
__global__ __launch_bounds__(128) void precompute_kernel(
    const float* __restrict__ inst, const float* __restrict__ anchor,
    const float* __restrict__ l2i, const float* __restrict__ img_wh,
    const float* __restrict__ enc_w, const float* __restrict__ enc_b,
    const float* __restrict__ kp_fixed, const float* __restrict__ kp_w,
    const float* __restrict__ kp_b)
{
    int n = blockIdx.x, t = threadIdx.x;
    int lane = t & 31, wid = t >> 5;
    __shared__ float inst_s[256];
    __shared__ float a_s[11];
    __shared__ float learn_s[18];
    __shared__ float kp_s[13][3];
    __shared__ float l2i_s[96];

    inst_s[t]       = inst[n * 256 + t];
    inst_s[t + 128] = inst[n * 256 + t + 128];
    if (t < 11) a_s[t] = anchor[n * 11 + t];
    if (t < 96) l2i_s[t] = l2i[t];
    __syncthreads();

    // X = instance_feature + anchor @ enc_w + enc_b
    for (int c = t; c < 256; c += 128) {
        float ae = enc_b[c];
        #pragma unroll
        for (int k = 0; k < 11; k++) ae += a_s[k] * enc_w[k * 256 + c];
        g_X[n * 256 + c] = inst_s[c] + ae;
    }
    // learnable keypoint offsets: warp-cooperative dot products (18 outputs)
    for (int j = wid; j < 18; j += 4) {
        float s = 0.f;
        #pragma unroll
        for (int q = 0; q < 8; q++) {
            int k = lane + q * 32;
            s += inst_s[k] * kp_w[k * 18 + j];
        }
        #pragma unroll
        for (int d = 16; d; d >>= 1) s += __shfl_xor_sync(0xffffffffu, s, d);
        if (lane == 0) learn_s[j] = s + kp_b[j];
    }
    __syncthreads();

    // 13 keypoints in 3D
    if (t < 13) {
        float ox, oy, oz;
        if (t < NUM_FIXED) { ox = kp_fixed[t*3]; oy = kp_fixed[t*3+1]; oz = kp_fixed[t*3+2]; }
        else { int j = t - NUM_FIXED; ox = learn_s[j*3]; oy = learn_s[j*3+1]; oz = learn_s[j*3+2]; }
        float sx = expf(a_s[3]), sy = expf(a_s[4]), sz = expf(a_s[5]);
        ox *= sx; oy *= sy; oz *= sz;
        float sn = a_s[6], cs = a_s[7];
        kp_s[t][0] = cs * ox - sn * oy + a_s[0];
        kp_s[t][1] = sn * ox + cs * oy + a_s[1];
        kp_s[t][2] = oz + a_s[2];
    }
    __syncthreads();

    // project to 6 cameras
    if (t < NUM_CAMS * NUM_PTS) {
        int cam = t / NUM_PTS, p = t % NUM_PTS;
        const float* M = &l2i_s[cam * 16];
        float x = kp_s[p][0], y = kp_s[p][1], z = kp_s[p][2];
        float px = M[0]*x + M[1]*y + M[2]*z  + M[3];
        float py = M[4]*x + M[5]*y + M[6]*z  + M[7];
        float pz = M[8]*x + M[9]*y + M[10]*z + M[11];
        float2 r;
        if (pz > 1e-5f) {
            float inv = 1.0f / pz;
            r.x = px * inv / img_wh[cam * 2 + 0];
            r.y = py * inv / img_wh[cam * 2 + 1];
        } else { r.x = -1e6f; r.y = -1e6f; }
        g_pts[(n * NUM_CAMS + cam) * NUM_PTS + p] = r;
    }
}

// ---------------- f32x2 tiled GEMM (big logits GEMM) ----------------
template <int BM, int BN, int BK, int TM, bool RESID>
__global__ __launch_bounds__((BM/TM)*(BN/8)) void gemm_f32x2_kernel(
    const float* __restrict__ A, const float* __restrict__ B,
    const float* __restrict__ bias, const float* __restrict__ resid,
    float* __restrict__ Cout, int M, int N, int K)
{
    constexpr int TX = BN / 8, TY = BM / TM, THREADS = TX * TY;
    constexpr int HALF = BN / 2;
    __shared__ unsigned long long As2[BK][BM];   // A duplicated into f32x2 pairs
    __shared__ float Bs[BK][BN];

    int tid = threadIdx.x;
    int tx = tid % TX, ty = tid / TX;
    int m0 = blockIdx.y * BM, n0 = blockIdx.x * BN;
    unsigned long long acc[TM][4] = {};          // 0ull == (0.0f, 0.0f)

    for (int k0 = 0; k0 < K; k0 += BK) {
        for (int i = tid * 4; i < BM * BK; i += THREADS * 4) {
            int m = i / BK, k = i % BK;
            float4 v = make_float4(0.f, 0.f, 0.f, 0.f);
            if (m0 + m < M) v = *(const float4*)&A[(m0 + m) * K + k0 + k];
            As2[k + 0][m] = pk2(v.x, v.x);
            As2[k + 1][m] = pk2(v.y, v.y);
            As2[k + 2][m] = pk2(v.z, v.z);
            As2[k + 3][m] = pk2(v.w, v.w);
        }
        for (int i = tid * 4; i < BK * BN; i += THREADS * 4) {
            int k = i / BN, nn = i % BN;
            float4 v = make_float4(0.f, 0.f, 0.f, 0.f);
            if (n0 + nn < N) v = *(const float4*)&B[(k0 + k) * N + n0 + nn];
            *(float4*)&Bs[k][nn] = v;
        }
        __syncthreads();
        #pragma unroll
        for (int k = 0; k < BK; k++) {
            unsigned long long a2[TM];
            #pragma unroll
            for (int i = 0; i < TM; i++) a2[i] = As2[k][ty * TM + i];
            ulonglong2 bA = *(const ulonglong2*)&Bs[k][tx * 4];
            ulonglong2 bB = *(const ulonglong2*)&Bs[k][HALF + tx * 4];
            #pragma unroll
            for (int i = 0; i < TM; i++) {
                fma2(acc[i][0], a2[i], bA.x);
                fma2(acc[i][1], a2[i], bA.y);
                fma2(acc[i][2], a2[i], bB.x);
                fma2(acc[i][3], a2[i], bB.y);
            }
        }
        __syncthreads();
    }
    #pragma unroll
    for (int i = 0; i < TM; i++) {
        int m = m0 + ty * TM + i;
        if (m >= M) continue;
        #pragma unroll
        for (int j = 0; j < 4; j++) {
            int nn = n0 + tx * 4 + 2 * (j & 1) + (j >> 1) * HALF;
            if (nn < N) {
                float lo, hi; upk2(acc[i][j], lo, hi);
                lo += bias[nn]; hi += bias[nn + 1];
                if (RESID) { lo += resid[m * N + nn]; hi += resid[m * N + nn + 1]; }
                *(float2*)&Cout[m * N + nn] = make_float2(lo, hi);
            }
        }
    }
}

// ---------------- split-K partial GEMM: one BK=32 chunk per block ----------------
// BM=32, BN=64, 256 threads; grid (N/64, ceil(M/32), KSPLIT); K/KSPLIT == 32
__global__ __launch_bounds__(256) void gemm_splitk_kernel(
    const float* __restrict__ A, const float* __restrict__ B,
    float* __restrict__ part, int M, int N, int K)
{
    constexpr int BM = 32, BN = 64, BK = 32;
    constexpr int TX = 16, THREADS = 256;
    __shared__ unsigned long long As2[BK][BM];
    __shared__ float Bs[BK][BN];

    int tid = threadIdx.x;
    int tx = tid % TX, ty = tid / TX;
    int m0 = blockIdx.y * BM, n0 = blockIdx.x * BN;
    int z  = blockIdx.z;
    int k0 = z * BK;
    unsigned long long acc0[2] = {}, acc1[2] = {};

    for (int i = tid * 4; i < BM * BK; i += THREADS * 4) {
        int m = i / BK, k = i % BK;
        float4 v = make_float4(0.f, 0.f, 0.f, 0.f);
        if (m0 + m < M) v = *(const float4*)&A[(m0 + m) * K + k0 + k];
        As2[k + 0][m] = pk2(v.x, v.x);
        As2[k + 1][m] = pk2(v.y, v.y);
        As2[k + 2][m] = pk2(v.z, v.z);
        As2[k + 3][m] = pk2(v.w, v.w);
    }
    for (int i = tid * 4; i < BK * BN; i += THREADS * 4) {
        int k = i / BN, nn = i % BN;
        *(float4*)&Bs[k][nn] = *(const float4*)&B[(k0 + k) * N + n0 + nn];
    }
    __syncthreads();
    #pragma unroll
    for (int k = 0; k < BK; k++) {
        unsigned long long a0 = As2[k][ty * 2], a1 = As2[k][ty * 2 + 1];
        ulonglong2 bA = *(const ulonglong2*)&Bs[k][tx * 4];
        fma2(acc0[0], a0, bA.x);
        fma2(acc0[1], a0, bA.y);
        fma2(acc1[0], a1, bA.x);
        fma2(acc1[1], a1, bA.y);
    }
    float* dst = part + z * (N_ANCHOR * C_DIM);
    #pragma unroll
    for (int i = 0; i < 2; i++) {
        int m = m0 + ty * 2 + i;
        if (m >= M) continue;
        float4 v;
        unsigned long long* acc = i ? acc1 : acc0;
        upk2(acc[0], v.x, v.y);
        upk2(acc[1], v.z, v.w);
        *(float4*)&dst[m * N + n0 + tx * 4] = v;
    }
}

// reduce: out = inst + bias + sum_z part[z]   (float4 over 900*256 elems)
__global__ __launch_bounds__(256) void splitk_reduce_kernel(
    const float* __restrict__ inst, const float* __restrict__ bias,
    float* __restrict__ out)
{
    int idx = blockIdx.x * 256 + threadIdx.x;          // float4 index, 57600 total
    if (idx >= (N_ANCHOR * C_DIM) / 4) return;
    int nb = (idx & 63) * 4;                            // column base (C=256 -> 64 float4/row)
    float4 b = *(const float4*)&bias[nb];
    float4 r = ((const float4*)inst)[idx];
    float4 o;
    o.x = r.x + b.x; o.y = r.y + b.y; o.z = r.z + b.z; o.w = r.w + b.w;
    #pragma unroll
    for (int z = 0; z < KSPLIT; z++) {
        float4 s = ((const float4*)g_part)[idx + z * 57600];
        o.x += s.x; o.y += s.y; o.z += s.z; o.w += s.w;
    }
    ((float4*)out)[idx] = o;
}

// ---------------- kernel 3: fused softmax + deformable gather/aggregate ----------------
__global__ __launch_bounds__(320) void agg_kernel(const float* __restrict__ feature)
{
    int n = blockIdx.x, tid = threadIdx.x;           // 320 threads = 10 warps
    int lane = tid & 31, wid = tid >> 5;
    __shared__ float  w_s[NW];                        // logits -> softmax weights
    __shared__ float2 pts_s[NUM_CAMS * NUM_PTS];
    __shared__ uint2  entries[NCOMBO * 4];            // packed (combo<<17|row), bw
    __shared__ int    warpTot[10], warpBase[11];
    __shared__ float4 red4[5 * 64];                   // cross-slice reduction

    for (int i = tid; i < NW; i += 320) w_s[i] = g_W[n * NW + i];
    if (tid < NUM_CAMS * NUM_PTS) pts_s[tid] = g_pts[n * NUM_CAMS * NUM_PTS + tid];
    __syncthreads();

    // fused softmax over 312 combos: warp g handles group g
    if (wid < 8) {
        int g = wid;
        float v[10]; int cnt = 0; float mx = -1e30f;
        for (int i = lane; i < NCOMBO; i += 32) { float x = w_s[i * 8 + g]; v[cnt++] = x; mx = fmaxf(mx, x); }
        #pragma unroll
        for (int d = 16; d; d >>= 1) mx = fmaxf(mx, __shfl_xor_sync(0xffffffffu, mx, d));
        float sum = 0.f;
        for (int j = 0; j < cnt; j++) { v[j] = __expf(v[j] - mx); sum += v[j]; }
        #pragma unroll
        for (int d = 16; d; d >>= 1) sum += __shfl_xor_sync(0xffffffffu, sum, d);
        float inv = 1.0f / sum;
        cnt = 0;
        for (int i = lane; i < NCOMBO; i += 32) w_s[i * 8 + g] = v[cnt++] * inv;
    }

    // phase 1: each thread = one (cam,lvl,pt) combo; collect valid corners
    int myCnt = 0;
    uint32_t pk[4]; float bws[4];
    if (tid < NCOMBO) {
        int cam = tid / (NUM_LEVELS * NUM_PTS);
        int r   = tid % (NUM_LEVELS * NUM_PTS);
        int lvl = r / NUM_PTS, p = r % NUM_PTS;
        float2 pt = pts_s[cam * NUM_PTS + p];
        int Wl = c_lvlW[lvl], Hl = c_lvlH[lvl], st = c_start[lvl];
        float x = pt.x * (float)Wl - 0.5f;
        float y = pt.y * (float)Hl - 0.5f;
        float xf = floorf(x), yf = floorf(y);
        int x0 = (int)xf, y0 = (int)yf;
        float fx = x - xf, fy = y - yf;
        #pragma unroll
        for (int j = 0; j < 4; j++) {
            int xi = x0 + (j & 1), yi = y0 + (j >> 1);
            float bw = ((j & 1) ? fx : 1.f - fx) * ((j & 2) ? fy : 1.f - fy);
            if (xi >= 0 && xi < Wl && yi >= 0 && yi < Hl && bw > 0.f) {
                int rowIdx = cam * SUM_HW + st + yi * Wl + xi;
                pk[myCnt]  = ((uint32_t)tid << 17) | (uint32_t)rowIdx;
                bws[myCnt] = bw;
                myCnt++;
            }
        }
    }

    // deterministic compaction: warp shfl scan + cross-warp scan
    int incl = myCnt;
    #pragma unroll
    for (int d = 1; d < 32; d <<= 1) {
        int v = __shfl_up_sync(0xffffffffu, incl, d);
        if (lane >= d) incl += v;
    }
    if (lane == 31) warpTot[wid] = incl;
    __syncthreads();
    if (tid < 32) {
        int v = (tid < 10) ? warpTot[tid] : 0;
        int inc2 = v;
        #pragma unroll
        for (int d = 1; d < 32; d <<= 1) {
            int u = __shfl_up_sync(0xffffffffu, inc2, d);
            if (lane >= d) inc2 += u;
        }
        if (tid < 10) warpBase[tid] = inc2 - v;
        if (tid == 9) warpBase[10] = inc2;   // total entry count
    }
    __syncthreads();
    int base = warpBase[wid] + incl - myCnt;
    for (int j = 0; j < myCnt; j++)
        entries[base + j] = make_uint2(pk[j], __float_as_uint(bws[j]));
    __syncthreads();

    // phase 2: 64 channel-slots (16B each) x 5 entry slices,
    // 4 independent gather chains per thread for MLP
    int nE = warpBase[10];
    int cslot = tid & 63;                       // channel base = cslot*4
    int s = tid >> 6;                           // slice 0..4 (warp-uniform)
    int g = cslot >> 3;                         // group
    const ulonglong2* fb = (const ulonglong2*)feature + cslot;
    unsigned long long p0a = 0ull, p0b = 0ull, p1a = 0ull, p1b = 0ull;
    unsigned long long p2a = 0ull, p2b = 0ull, p3a = 0ull, p3b = 0ull;
    int i = s;
    for (; i + 15 < nE; i += 20) {
        uint2 e0 = entries[i];
        uint2 e1 = entries[i + 5];
        uint2 e2 = entries[i + 10];
        uint2 e3 = entries[i + 15];
        float w0 = __uint_as_float(e0.y) * w_s[(e0.x >> 17) * 8 + g];
        float w1 = __uint_as_float(e1.y) * w_s[(e1.x >> 17) * 8 + g];
        float w2 = __uint_as_float(e2.y) * w_s[(e2.x >> 17) * 8 + g];
        float w3 = __uint_as_float(e3.y) * w_s[(e3.x >> 17) * 8 + g];
        ulonglong2 f0 = __ldg(&fb[(e0.x & 0x1FFFFu) * 64u]);
        ulonglong2 f1 = __ldg(&fb[(e1.x & 0x1FFFFu) * 64u]);
        ulonglong2 f2 = __ldg(&fb[(e2.x & 0x1FFFFu) * 64u]);
        ulonglong2 f3 = __ldg(&fb[(e3.x & 0x1FFFFu) * 64u]);
        unsigned long long w02 = pk2(w0, w0), w12 = pk2(w1, w1);
        unsigned long long w22 = pk2(w2, w2), w32 = pk2(w3, w3);
        fma2(p0a, w02, f0.x); fma2(p0b, w02, f0.y);
        fma2(p1a, w12, f1.x); fma2(p1b, w12, f1.y);
        fma2(p2a, w22, f2.x); fma2(p2b, w22, f2.y);
        fma2(p3a, w32, f3.x); fma2(p3b, w32, f3.y);
    }
    for (; i < nE; i += 5) {
        uint2 e = entries[i];
        float wv = __uint_as_float(e.y) * w_s[(e.x >> 17) * 8 + g];
        unsigned long long wv2 = pk2(wv, wv);
        ulonglong2 f = __ldg(&fb[(e.x & 0x1FFFFu) * 64u]);
        fma2(p0a, wv2, f.x);
        fma2(p0b, wv2, f.y);
    }
    {
        float x0, y0, x1, y1, x2, y2, x3, y3;
        float4 accv;
        upk2(p0a, x0, y0); upk2(p1a, x1, y1); upk2(p2a, x2, y2); upk2(p3a, x3, y3);
        accv.x = (x0 + x1) + (x2 + x3);
        accv.y = (y0 + y1) + (y2 + y3);
        upk2(p0b, x0, y0); upk2(p1b, x1, y1); upk2(p2b, x2, y2); upk2(p3b, x3, y3);
        accv.z = (x0 + x1) + (x2 + x3);
        accv.w = (y0 + y1) + (y2 + y3);
        red4[s * 64 + cslot] = accv;
    }
    __syncthreads();
    if (tid < 256) {
        const float* rf = (const float*)red4;
        float sum = rf[tid] + rf[256 + tid] + rf[512 + tid] + rf[768 + tid] + rf[1024 + tid];
        g_agg[n * 256 + tid] = sum;
    }
}

// ---------------- launch ----------------
extern "C" void kernel_launch(void* const* d_in, const int* in_sizes, int n_in,
                              void* d_out, int out_size)
{
    const float* inst     = (const float*)d_in[0];
    const float* anchor   = (const float*)d_in[1];
    // d_in[2] time_interval unused
    const float* feature  = (const float*)d_in[3];
    // d_in[4] spatial_shapes, d_in[5] level_start_index: hardcoded constants
    const float* l2i      = (const float*)d_in[6];
    const float* img_wh   = (const float*)d_in[7];
    const float* enc_w    = (const float*)d_in[8];
    const float* enc_b    = (const float*)d_in[9];
    const float* kp_fixed = (const float*)d_in[10];
    const float* kp_w     = (const float*)d_in[11];
    const float* kp_b     = (const float*)d_in[12];
    const float* wfc_w    = (const float*)d_in[13];
    const float* wfc_b    = (const float*)d_in[14];
    const float* out_w    = (const float*)d_in[15];
    const float* out_b    = (const float*)d_in[16];
    float* out = (float*)d_out;

    float *pX, *pW, *pAgg, *pPart;
    cudaGetSymbolAddress((void**)&pX, g_X);
    cudaGetSymbolAddress((void**)&pW, g_W);
    cudaGetSymbolAddress((void**)&pAgg, g_agg);
    cudaGetSymbolAddress((void**)&pPart, g_part);

    precompute_kernel<<<N_ANCHOR, 128>>>(inst, anchor, l2i, img_wh,
                                         enc_w, enc_b, kp_fixed, kp_w, kp_b);
    // logits = X @ wfc_w + wfc_b : (900 x 2496), K=256 — TM=2 -> 512 thr, 32 warps/SM
    gemm_f32x2_kernel<64, 128, 32, 2, false><<<dim3(20, 15), 512>>>(
        pX, wfc_w, wfc_b, nullptr, pW, N_ANCHOR, NW, C_DIM);
    agg_kernel<<<N_ANCHOR, 320>>>(feature);
    // out = inst + agg @ out_w + out_b : split-K=8 partials + reduce
    gemm_splitk_kernel<<<dim3(4, 29, KSPLIT), 256>>>(
        pAgg, out_w, pPart, N_ANCHOR, C_DIM, C_DIM);
    splitk_reduce_kernel<<<225, 256>>>(inst, out_b, out);
}

// round 12
// speedup vs baseline: 1.1658x; 1.1658x over previous
#include <cuda_runtime.h>
#include <cstdint>

#define N_ANCHOR   900
#define C_DIM      256
#define NUM_CAMS   6
#define NUM_LEVELS 4
#define NUM_PTS    13
#define NUM_FIXED  7
#define NUM_LEARN  6
#define NUM_GROUPS 8
#define NW         2496   // 6*4*13*8
#define NCOMBO     312    // 6*4*13
#define SUM_HW     14960

__constant__ int c_lvlW[4]   = {176, 88, 44, 22};
__constant__ int c_lvlH[4]   = {64, 32, 16, 8};
__constant__ int c_start[4]  = {0, 11264, 14080, 14784};

// ---------------- scratch (device globals; no allocation) ----------------
__device__ float  g_X[N_ANCHOR * C_DIM];                      // inst + anchor_embed
__device__ float2 g_pts[N_ANCHOR * NUM_CAMS * NUM_PTS];       // normalized 2D pts
__device__ float  g_W[N_ANCHOR * NW];                         // raw logits (softmax fused into agg)
__device__ float  g_agg[N_ANCHOR * C_DIM];                    // aggregated features

// ---------------- f32x2 helpers ----------------
__device__ __forceinline__ unsigned long long pk2(float lo, float hi) {
    unsigned long long r;
    asm("mov.b64 %0, {%1, %2};" : "=l"(r) : "f"(lo), "f"(hi));
    return r;
}
__device__ __forceinline__ void upk2(unsigned long long v, float& lo, float& hi) {
    asm("mov.b64 {%0, %1}, %2;" : "=f"(lo), "=f"(hi) : "l"(v));
}
__device__ __forceinline__ void fma2(unsigned long long& d, unsigned long long a, unsigned long long b) {
    asm("fma.rn.f32x2 %0, %1, %2, %0;" : "+l"(d) : "l"(a), "l"(b));
}

// ---------------- kernel 1: embed + keypoints + projection ----------------
__global__ __launch_bounds__(128) void precompute_kernel(
    const float* __restrict__ inst, const float* __restrict__ anchor,
    const float* __restrict__ l2i, const float* __restrict__ img_wh,
    const float* __restrict__ enc_w, const float* __restrict__ enc_b,
    const float* __restrict__ kp_fixed, const float* __restrict__ kp_w,
    const float* __restrict__ kp_b)
{
    int n = blockIdx.x, t = threadIdx.x;
    int lane = t & 31, wid = t >> 5;
    __shared__ float inst_s[256];
    __shared__ float a_s[11];
    __shared__ float learn_s[18];
    __shared__ float kp_s[13][3];
    __shared__ float l2i_s[96];

    inst_s[t]       = inst[n * 256 + t];
    inst_s[t + 128] = inst[n * 256 + t + 128];
    if (t < 11) a_s[t] = anchor[n * 11 + t];
    if (t < 96) l2i_s[t] = l2i[t];
    __syncthreads();

    // X = instance_feature + anchor @ enc_w + enc_b
    for (int c = t; c < 256; c += 128) {
        float ae = enc_b[c];
        #pragma unroll
        for (int k = 0; k < 11; k++) ae += a_s[k] * enc_w[k * 256 + c];
        g_X[n * 256 + c] = inst_s[c] + ae;
    }
    // learnable keypoint offsets: warp-cooperative dot products (18 outputs)
    for (int j = wid; j < 18; j += 4) {
        float s = 0.f;
        #pragma unroll
        for (int q = 0; q < 8; q++) {
            int k = lane + q * 32;
            s += inst_s[k] * kp_w[k * 18 + j];
        }
        #pragma unroll
        for (int d = 16; d; d >>= 1) s += __shfl_xor_sync(0xffffffffu, s, d);
        if (lane == 0) learn_s[j] = s + kp_b[j];
    }
    __syncthreads();

    // 13 keypoints in 3D
    if (t < 13) {
        float ox, oy, oz;
        if (t < NUM_FIXED) { ox = kp_fixed[t*3]; oy = kp_fixed[t*3+1]; oz = kp_fixed[t*3+2]; }
        else { int j = t - NUM_FIXED; ox = learn_s[j*3]; oy = learn_s[j*3+1]; oz = learn_s[j*3+2]; }
        float sx = expf(a_s[3]), sy = expf(a_s[4]), sz = expf(a_s[5]);
        ox *= sx; oy *= sy; oz *= sz;
        float sn = a_s[6], cs = a_s[7];
        kp_s[t][0] = cs * ox - sn * oy + a_s[0];
        kp_s[t][1] = sn * ox + cs * oy + a_s[1];
        kp_s[t][2] = oz + a_s[2];
    }
    __syncthreads();

    // project to 6 cameras
    if (t < NUM_CAMS * NUM_PTS) {
        int cam = t / NUM_PTS, p = t % NUM_PTS;
        const float* M = &l2i_s[cam * 16];
        float x = kp_s[p][0], y = kp_s[p][1], z = kp_s[p][2];
        float px = M[0]*x + M[1]*y + M[2]*z  + M[3];
        float py = M[4]*x + M[5]*y + M[6]*z  + M[7];
        float pz = M[8]*x + M[9]*y + M[10]*z + M[11];
        float2 r;
        if (pz > 1e-5f) {
            float inv = 1.0f / pz;
            r.x = px * inv / img_wh[cam * 2 + 0];
            r.y = py * inv / img_wh[cam * 2 + 1];
        } else { r.x = -1e6f; r.y = -1e6f; }
        g_pts[(n * NUM_CAMS + cam) * NUM_PTS + p] = r;
    }
}

// ---------------- double-buffered f32x2 GEMM (big logits GEMM) ----------------
// BM=64, BN=128, BK=32, TM=4, TN=8, 256 threads; register-staged prefetch
// overlaps the next tile's global loads with the current tile's FMA work.
template <int BM, int BN, int BK, int TM>
__global__ __launch_bounds__((BM/TM)*(BN/8), 2) void gemm_db_kernel(
    const float* __restrict__ A, const float* __restrict__ B,
    const float* __restrict__ bias, float* __restrict__ Cout,
    int M, int N, int K)
{
    constexpr int TX = BN / 8, TY = BM / TM, THREADS = TX * TY;
    constexpr int HALF = BN / 2;
    constexpr int NA = (BM * BK) / (THREADS * 4);   // A float4 loads / thread
    constexpr int NB = (BK * BN) / (THREADS * 4);   // B float4 loads / thread
    static_assert(NA * THREADS * 4 == BM * BK, "A tile divisibility");
    static_assert(NB * THREADS * 4 == BK * BN, "B tile divisibility");
    __shared__ unsigned long long As2[BK][BM];   // A duplicated into f32x2 pairs
    __shared__ float Bs[BK][BN];

    int tid = threadIdx.x;
    int tx = tid % TX, ty = tid / TX;
    int m0 = blockIdx.y * BM, n0 = blockIdx.x * BN;
    unsigned long long acc[TM][4] = {};
    float4 aR[NA], bR[NB];

    // prologue: stage tile 0 in registers
    #pragma unroll
    for (int u = 0; u < NA; u++) {
        int i = tid * 4 + u * THREADS * 4;
        int m = i / BK, k = i % BK;
        aR[u] = (m0 + m < M) ? *(const float4*)&A[(m0 + m) * K + k]
                             : make_float4(0.f, 0.f, 0.f, 0.f);
    }
    #pragma unroll
    for (int u = 0; u < NB; u++) {
        int i = tid * 4 + u * THREADS * 4;
        int k = i / BN, nn = i % BN;
        bR[u] = (n0 + nn < N) ? *(const float4*)&B[k * N + n0 + nn]
                              : make_float4(0.f, 0.f, 0.f, 0.f);
    }

    int nk = K / BK;
    for (int t = 0; t < nk; t++) {
        // commit staged tile to smem
        #pragma unroll
        for (int u = 0; u < NA; u++) {
            int i = tid * 4 + u * THREADS * 4;
            int m = i / BK, k = i % BK;
            As2[k + 0][m] = pk2(aR[u].x, aR[u].x);
            As2[k + 1][m] = pk2(aR[u].y, aR[u].y);
            As2[k + 2][m] = pk2(aR[u].z, aR[u].z);
            As2[k + 3][m] = pk2(aR[u].w, aR[u].w);
        }
        #pragma unroll
        for (int u = 0; u < NB; u++) {
            int i = tid * 4 + u * THREADS * 4;
            int k = i / BN, nn = i % BN;
            *(float4*)&Bs[k][nn] = bR[u];
        }
        __syncthreads();

        // prefetch next tile (LDGs in flight during compute)
        if (t + 1 < nk) {
            int k0n = (t + 1) * BK;
            #pragma unroll
            for (int u = 0; u < NA; u++) {
                int i = tid * 4 + u * THREADS * 4;
                int m = i / BK, k = i % BK;
                aR[u] = (m0 + m < M) ? *(const float4*)&A[(m0 + m) * K + k0n + k]
                                     : make_float4(0.f, 0.f, 0.f, 0.f);
            }
            #pragma unroll
            for (int u = 0; u < NB; u++) {
                int i = tid * 4 + u * THREADS * 4;
                int k = i / BN, nn = i % BN;
                bR[u] = (n0 + nn < N) ? *(const float4*)&B[(k0n + k) * N + n0 + nn]
                                      : make_float4(0.f, 0.f, 0.f, 0.f);
            }
        }

        // compute current tile
        #pragma unroll
        for (int k = 0; k < BK; k++) {
            unsigned long long a2[TM];
            #pragma unroll
            for (int i = 0; i < TM; i++) a2[i] = As2[k][ty * TM + i];
            ulonglong2 bA = *(const ulonglong2*)&Bs[k][tx * 4];
            ulonglong2 bB = *(const ulonglong2*)&Bs[k][HALF + tx * 4];
            #pragma unroll
            for (int i = 0; i < TM; i++) {
                fma2(acc[i][0], a2[i], bA.x);
                fma2(acc[i][1], a2[i], bA.y);
                fma2(acc[i][2], a2[i], bB.x);
                fma2(acc[i][3], a2[i], bB.y);
            }
        }
        __syncthreads();
    }
    // epilogue
    #pragma unroll
    for (int i = 0; i < TM; i++) {
        int m = m0 + ty * TM + i;
        if (m >= M) continue;
        #pragma unroll
        for (int j = 0; j < 4; j++) {
            int nn = n0 + tx * 4 + 2 * (j & 1) + (j >> 1) * HALF;
            if (nn < N) {
                float lo, hi; upk2(acc[i][j], lo, hi);
                lo += bias[nn]; hi += bias[nn + 1];
                *(float2*)&Cout[m * N + nn] = make_float2(lo, hi);
            }
        }
    }
}

// ---------------- generic f32x2 tiled GEMM (final GEMM, TN=2) ----------------
template <int BM, int BN, int BK, int TM, int TN, bool RESID>
__global__ __launch_bounds__((BM/TM)*(BN/TN)) void gemm_f32x2_kernel(
    const float* __restrict__ A, const float* __restrict__ B,
    const float* __restrict__ bias, const float* __restrict__ resid,
    float* __restrict__ Cout, int M, int N, int K)
{
    constexpr int TX = BN / TN, TY = BM / TM, THREADS = TX * TY;
    constexpr int HALF = BN / 2;
    constexpr int NACC = TN / 2;
    __shared__ unsigned long long As2[BK][BM];
    __shared__ float Bs[BK][BN];

    int tid = threadIdx.x;
    int tx = tid % TX, ty = tid / TX;
    int m0 = blockIdx.y * BM, n0 = blockIdx.x * BN;
    unsigned long long acc[TM][NACC] = {};

    for (int k0 = 0; k0 < K; k0 += BK) {
        for (int i = tid * 4; i < BM * BK; i += THREADS * 4) {
            int m = i / BK, k = i % BK;
            float4 v = make_float4(0.f, 0.f, 0.f, 0.f);
            if (m0 + m < M) v = *(const float4*)&A[(m0 + m) * K + k0 + k];
            As2[k + 0][m] = pk2(v.x, v.x);
            As2[k + 1][m] = pk2(v.y, v.y);
            As2[k + 2][m] = pk2(v.z, v.z);
            As2[k + 3][m] = pk2(v.w, v.w);
        }
        for (int i = tid * 4; i < BK * BN; i += THREADS * 4) {
            int k = i / BN, nn = i % BN;
            float4 v = make_float4(0.f, 0.f, 0.f, 0.f);
            if (n0 + nn < N) v = *(const float4*)&B[(k0 + k) * N + n0 + nn];
            *(float4*)&Bs[k][nn] = v;
        }
        __syncthreads();
        #pragma unroll
        for (int k = 0; k < BK; k++) {
            unsigned long long a2[TM];
            #pragma unroll
            for (int i = 0; i < TM; i++) a2[i] = As2[k][ty * TM + i];
            unsigned long long bf[NACC];
            if constexpr (TN == 8) {
                ulonglong2 bA = *(const ulonglong2*)&Bs[k][tx * 4];
                ulonglong2 bB = *(const ulonglong2*)&Bs[k][HALF + tx * 4];
                bf[0] = bA.x; bf[1] = bA.y; bf[2] = bB.x; bf[3] = bB.y;
            } else if constexpr (TN == 4) {
                ulonglong2 bA = *(const ulonglong2*)&Bs[k][tx * 4];
                bf[0] = bA.x; bf[1] = bA.y;
            } else {
                bf[0] = *(const unsigned long long*)&Bs[k][tx * 2];
            }
            #pragma unroll
            for (int i = 0; i < TM; i++)
                #pragma unroll
                for (int j = 0; j < NACC; j++) fma2(acc[i][j], a2[i], bf[j]);
        }
        __syncthreads();
    }
    #pragma unroll
    for (int i = 0; i < TM; i++) {
        int m = m0 + ty * TM + i;
        if (m >= M) continue;
        #pragma unroll
        for (int j = 0; j < NACC; j++) {
            int nn;
            if constexpr (TN == 8)      nn = n0 + tx * 4 + 2 * (j & 1) + (j >> 1) * HALF;
            else if constexpr (TN == 4) nn = n0 + tx * 4 + 2 * j;
            else                        nn = n0 + tx * 2;
            if (nn < N) {
                float lo, hi; upk2(acc[i][j], lo, hi);
                lo += bias[nn]; hi += bias[nn + 1];
                if (RESID) { lo += resid[m * N + nn]; hi += resid[m * N + nn + 1]; }
                *(float2*)&Cout[m * N + nn] = make_float2(lo, hi);
            }
        }
    }
}

// ---------------- kernel 3: fused softmax + deformable gather/aggregate ----------------
__global__ __launch_bounds__(320) void agg_kernel(const float* __restrict__ feature)
{
    int n = blockIdx.x, tid = threadIdx.x;           // 320 threads = 10 warps
    int lane = tid & 31, wid = tid >> 5;
    __shared__ float  w_s[NW];                        // logits -> softmax weights
    __shared__ float2 pts_s[NUM_CAMS * NUM_PTS];
    __shared__ uint2  entries[NCOMBO * 4];            // packed (combo<<17|row), bw
    __shared__ int    warpTot[10], warpBase[11];
    __shared__ float4 red4[5 * 64];                   // cross-slice reduction

    for (int i = tid; i < NW; i += 320) w_s[i] = g_W[n * NW + i];
    if (tid < NUM_CAMS * NUM_PTS) pts_s[tid] = g_pts[n * NUM_CAMS * NUM_PTS + tid];
    __syncthreads();

    // fused softmax over 312 combos: warp g handles group g
    if (wid < 8) {
        int g = wid;
        float v[10]; int cnt = 0; float mx = -1e30f;
        for (int i = lane; i < NCOMBO; i += 32) { float x = w_s[i * 8 + g]; v[cnt++] = x; mx = fmaxf(mx, x); }
        #pragma unroll
        for (int d = 16; d; d >>= 1) mx = fmaxf(mx, __shfl_xor_sync(0xffffffffu, mx, d));
        float sum = 0.f;
        for (int j = 0; j < cnt; j++) { v[j] = __expf(v[j] - mx); sum += v[j]; }
        #pragma unroll
        for (int d = 16; d; d >>= 1) sum += __shfl_xor_sync(0xffffffffu, sum, d);
        float inv = 1.0f / sum;
        cnt = 0;
        for (int i = lane; i < NCOMBO; i += 32) w_s[i * 8 + g] = v[cnt++] * inv;
    }

    // phase 1: each thread = one (cam,lvl,pt) combo; collect valid corners
    int myCnt = 0;
    uint32_t pk[4]; float bws[4];
    if (tid < NCOMBO) {
        int cam = tid / (NUM_LEVELS * NUM_PTS);
        int r   = tid % (NUM_LEVELS * NUM_PTS);
        int lvl = r / NUM_PTS, p = r % NUM_PTS;
        float2 pt = pts_s[cam * NUM_PTS + p];
        int Wl = c_lvlW[lvl], Hl = c_lvlH[lvl], st = c_start[lvl];
        float x = pt.x * (float)Wl - 0.5f;
        float y = pt.y * (float)Hl - 0.5f;
        float xf = floorf(x), yf = floorf(y);
        int x0 = (int)xf, y0 = (int)yf;
        float fx = x - xf, fy = y - yf;
        #pragma unroll
        for (int j = 0; j < 4; j++) {
            int xi = x0 + (j & 1), yi = y0 + (j >> 1);
            float bw = ((j & 1) ? fx : 1.f - fx) * ((j & 2) ? fy : 1.f - fy);
            if (xi >= 0 && xi < Wl && yi >= 0 && yi < Hl && bw > 0.f) {
                int rowIdx = cam * SUM_HW + st + yi * Wl + xi;
                pk[myCnt]  = ((uint32_t)tid << 17) | (uint32_t)rowIdx;
                bws[myCnt] = bw;
                myCnt++;
            }
        }
    }

    // deterministic compaction: warp shfl scan + cross-warp scan
    int incl = myCnt;
    #pragma unroll
    for (int d = 1; d < 32; d <<= 1) {
        int v = __shfl_up_sync(0xffffffffu, incl, d);
        if (lane >= d) incl += v;
    }
    if (lane == 31) warpTot[wid] = incl;
    __syncthreads();
    if (tid < 32) {
        int v = (tid < 10) ? warpTot[tid] : 0;
        int inc2 = v;
        #pragma unroll
        for (int d = 1; d < 32; d <<= 1) {
            int u = __shfl_up_sync(0xffffffffu, inc2, d);
            if (lane >= d) inc2 += u;
        }
        if (tid < 10) warpBase[tid] = inc2 - v;
        if (tid == 9) warpBase[10] = inc2;   // total entry count
    }
    __syncthreads();
    int base = warpBase[wid] + incl - myCnt;
    for (int j = 0; j < myCnt; j++)
        entries[base + j] = make_uint2(pk[j], __float_as_uint(bws[j]));
    __syncthreads();

    // phase 2: 64 channel-slots (16B each) x 5 entry slices, f32x2 accumulate
    int nE = warpBase[10];
    int cslot = tid & 63;                       // channel base = cslot*4
    int s = tid >> 6;                           // slice 0..4 (warp-uniform)
    int g = cslot >> 3;                         // group
    const ulonglong2* fb = (const ulonglong2*)feature + cslot;
    unsigned long long a0 = 0ull, a1 = 0ull;
    #pragma unroll 2
    for (int i = s; i < nE; i += 5) {
        uint2 e = entries[i];
        uint32_t rowIdx = e.x & 0x1FFFFu;
        float wv = __uint_as_float(e.y) * w_s[(e.x >> 17) * 8 + g];
        unsigned long long wv2 = pk2(wv, wv);
        ulonglong2 f = __ldg(&fb[rowIdx * 64u]);
        fma2(a0, wv2, f.x);
        fma2(a1, wv2, f.y);
    }
    {
        float4 accv;
        upk2(a0, accv.x, accv.y);
        upk2(a1, accv.z, accv.w);
        red4[s * 64 + cslot] = accv;
    }
    __syncthreads();
    if (tid < 256) {
        const float* rf = (const float*)red4;
        float sum = rf[tid] + rf[256 + tid] + rf[512 + tid] + rf[768 + tid] + rf[1024 + tid];
        g_agg[n * 256 + tid] = sum;
    }
}

// ---------------- launch ----------------
extern "C" void kernel_launch(void* const* d_in, const int* in_sizes, int n_in,
                              void* d_out, int out_size)
{
    const float* inst     = (const float*)d_in[0];
    const float* anchor   = (const float*)d_in[1];
    // d_in[2] time_interval unused
    const float* feature  = (const float*)d_in[3];
    // d_in[4] spatial_shapes, d_in[5] level_start_index: hardcoded constants
    const float* l2i      = (const float*)d_in[6];
    const float* img_wh   = (const float*)d_in[7];
    const float* enc_w    = (const float*)d_in[8];
    const float* enc_b    = (const float*)d_in[9];
    const float* kp_fixed = (const float*)d_in[10];
    const float* kp_w     = (const float*)d_in[11];
    const float* kp_b     = (const float*)d_in[12];
    const float* wfc_w    = (const float*)d_in[13];
    const float* wfc_b    = (const float*)d_in[14];
    const float* out_w    = (const float*)d_in[15];
    const float* out_b    = (const float*)d_in[16];
    float* out = (float*)d_out;

    float *pX, *pW, *pAgg;
    cudaGetSymbolAddress((void**)&pX, g_X);
    cudaGetSymbolAddress((void**)&pW, g_W);
    cudaGetSymbolAddress((void**)&pAgg, g_agg);

    precompute_kernel<<<N_ANCHOR, 128>>>(inst, anchor, l2i, img_wh,
                                         enc_w, enc_b, kp_fixed, kp_w, kp_b);
    // logits = X @ wfc_w + wfc_b : (900 x 2496), K=256 — double-buffered
    gemm_db_kernel<64, 128, 32, 4><<<dim3(20, 15), 256>>>(
        pX, wfc_w, wfc_b, pW, N_ANCHOR, NW, C_DIM);
    agg_kernel<<<N_ANCHOR, 320>>>(feature);
    // out = inst + agg @ out_w + out_b : (900 x 256), K=256 (R6 best shape)
    gemm_f32x2_kernel<64, 32, 32, 2, 2, true><<<dim3(8, 15), 512>>>(
        pAgg, out_w, out_b, inst, out, N_ANCHOR, C_DIM, C_DIM);
}

// round 13
// speedup vs baseline: 1.2086x; 1.0367x over previous
#include <cuda_runtime.h>
#include <cstdint>

#define N_ANCHOR   900
#define C_DIM      256
#define NUM_CAMS   6
#define NUM_LEVELS 4
#define NUM_PTS    13
#define NUM_FIXED  7
#define NUM_LEARN  6
#define NUM_GROUPS 8
#define NW         2496   // 6*4*13*8
#define NCOMBO     312    // 6*4*13
#define SUM_HW     14960
#define KSPLIT     8

__constant__ int c_lvlW[4]   = {176, 88, 44, 22};
__constant__ int c_lvlH[4]   = {64, 32, 16, 8};
__constant__ int c_start[4]  = {0, 11264, 14080, 14784};

// ---------------- scratch (device globals; no allocation) ----------------
__device__ float  g_X[N_ANCHOR * C_DIM];                      // inst + anchor_embed
__device__ float2 g_pts[N_ANCHOR * NUM_CAMS * NUM_PTS];       // normalized 2D pts
__device__ float  g_W[N_ANCHOR * NW];                         // raw logits (softmax fused into agg)
__device__ float  g_agg[N_ANCHOR * C_DIM];                    // aggregated features
__device__ float  g_part[KSPLIT * N_ANCHOR * C_DIM];          // split-K partials

// ---------------- f32x2 helpers ----------------
__device__ __forceinline__ unsigned long long pk2(float lo, float hi) {
    unsigned long long r;
    asm("mov.b64 %0, {%1, %2};" : "=l"(r) : "f"(lo), "f"(hi));
    return r;
}
__device__ __forceinline__ void upk2(unsigned long long v, float& lo, float& hi) {
    asm("mov.b64 {%0, %1}, %2;" : "=f"(lo), "=f"(hi) : "l"(v));
}
__device__ __forceinline__ void fma2(unsigned long long& d, unsigned long long a, unsigned long long b) {
    asm("fma.rn.f32x2 %0, %1, %2, %0;" : "+l"(d) : "l"(a), "l"(b));
}

// ---------------- kernel 1: embed + keypoints + projection ----------------
__global__ __launch_bounds__(128) void precompute_kernel(
    const float* __restrict__ inst, const float* __restrict__ anchor,
    const float* __restrict__ l2i, const float* __restrict__ img_wh,
    const float* __restrict__ enc_w, const float* __restrict__ enc_b,
    const float* __restrict__ kp_fixed, const float* __restrict__ kp_w,
    const float* __restrict__ kp_b)
{
    int n = blockIdx.x, t = threadIdx.x;
    int lane = t & 31, wid = t >> 5;
    __shared__ float inst_s[256];
    __shared__ float a_s[11];
    __shared__ float learn_s[18];
    __shared__ float kp_s[13][3];
    __shared__ float l2i_s[96];

    inst_s[t]       = inst[n * 256 + t];
    inst_s[t + 128] = inst[n * 256 + t + 128];
    if (t < 11) a_s[t] = anchor[n * 11 + t];
    if (t < 96) l2i_s[t] = l2i[t];
    __syncthreads();

    // X = instance_feature + anchor @ enc_w + enc_b
    for (int c = t; c < 256; c += 128) {
        float ae = enc_b[c];
        #pragma unroll
        for (int k = 0; k < 11; k++) ae += a_s[k] * enc_w[k * 256 + c];
        g_X[n * 256 + c] = inst_s[c] + ae;
    }
    // learnable keypoint offsets: warp-cooperative dot products (18 outputs)
    for (int j = wid; j < 18; j += 4) {
        float s = 0.f;
        #pragma unroll
        for (int q = 0; q < 8; q++) {
            int k = lane + q * 32;
            s += inst_s[k] * kp_w[k * 18 + j];
        }
        #pragma unroll
        for (int d = 16; d; d >>= 1) s += __shfl_xor_sync(0xffffffffu, s, d);
        if (lane == 0) learn_s[j] = s + kp_b[j];
    }
    __syncthreads();

    // 13 keypoints in 3D
    if (t < 13) {
        float ox, oy, oz;
        if (t < NUM_FIXED) { ox = kp_fixed[t*3]; oy = kp_fixed[t*3+1]; oz = kp_fixed[t*3+2]; }
        else { int j = t - NUM_FIXED; ox = learn_s[j*3]; oy = learn_s[j*3+1]; oz = learn_s[j*3+2]; }
        float sx = expf(a_s[3]), sy = expf(a_s[4]), sz = expf(a_s[5]);
        ox *= sx; oy *= sy; oz *= sz;
        float sn = a_s[6], cs = a_s[7];
        kp_s[t][0] = cs * ox - sn * oy + a_s[0];
        kp_s[t][1] = sn * ox + cs * oy + a_s[1];
        kp_s[t][2] = oz + a_s[2];
    }
    __syncthreads();

    // project to 6 cameras
    if (t < NUM_CAMS * NUM_PTS) {
        int cam = t / NUM_PTS, p = t % NUM_PTS;
        const float* M = &l2i_s[cam * 16];
        float x = kp_s[p][0], y = kp_s[p][1], z = kp_s[p][2];
        float px = M[0]*x + M[1]*y + M[2]*z  + M[3];
        float py = M[4]*x + M[5]*y + M[6]*z  + M[7];
        float pz = M[8]*x + M[9]*y + M[10]*z + M[11];
        float2 r;
        if (pz > 1e-5f) {
            float inv = 1.0f / pz;
            r.x = px * inv / img_wh[cam * 2 + 0];
            r.y = py * inv / img_wh[cam * 2 + 1];
        } else { r.x = -1e6f; r.y = -1e6f; }
        g_pts[(n * NUM_CAMS + cam) * NUM_PTS + p] = r;
    }
}

// ---------------- double-buffered f32x2 GEMM (big logits GEMM) ----------------
// BM=64, BN=128, BK=32, TM=4, TN=8, 256 threads; register-staged prefetch
// overlaps the next tile's global loads with the current tile's FMA work.
template <int BM, int BN, int BK, int TM>
__global__ __launch_bounds__((BM/TM)*(BN/8), 2) void gemm_db_kernel(
    const float* __restrict__ A, const float* __restrict__ B,
    const float* __restrict__ bias, float* __restrict__ Cout,
    int M, int N, int K)
{
    constexpr int TX = BN / 8, TY = BM / TM, THREADS = TX * TY;
    constexpr int HALF = BN / 2;
    constexpr int NA = (BM * BK) / (THREADS * 4);   // A float4 loads / thread
    constexpr int NB = (BK * BN) / (THREADS * 4);   // B float4 loads / thread
    static_assert(NA * THREADS * 4 == BM * BK, "A tile divisibility");
    static_assert(NB * THREADS * 4 == BK * BN, "B tile divisibility");
    __shared__ unsigned long long As2[BK][BM];   // A duplicated into f32x2 pairs
    __shared__ float Bs[BK][BN];

    int tid = threadIdx.x;
    int tx = tid % TX, ty = tid / TX;
    int m0 = blockIdx.y * BM, n0 = blockIdx.x * BN;
    unsigned long long acc[TM][4] = {};
    float4 aR[NA], bR[NB];

    // prologue: stage tile 0 in registers
    #pragma unroll
    for (int u = 0; u < NA; u++) {
        int i = tid * 4 + u * THREADS * 4;
        int m = i / BK, k = i % BK;
        aR[u] = (m0 + m < M) ? *(const float4*)&A[(m0 + m) * K + k]
                             : make_float4(0.f, 0.f, 0.f, 0.f);
    }
    #pragma unroll
    for (int u = 0; u < NB; u++) {
        int i = tid * 4 + u * THREADS * 4;
        int k = i / BN, nn = i % BN;
        bR[u] = (n0 + nn < N) ? *(const float4*)&B[k * N + n0 + nn]
                              : make_float4(0.f, 0.f, 0.f, 0.f);
    }

    int nk = K / BK;
    for (int t = 0; t < nk; t++) {
        // commit staged tile to smem
        #pragma unroll
        for (int u = 0; u < NA; u++) {
            int i = tid * 4 + u * THREADS * 4;
            int m = i / BK, k = i % BK;
            As2[k + 0][m] = pk2(aR[u].x, aR[u].x);
            As2[k + 1][m] = pk2(aR[u].y, aR[u].y);
            As2[k + 2][m] = pk2(aR[u].z, aR[u].z);
            As2[k + 3][m] = pk2(aR[u].w, aR[u].w);
        }
        #pragma unroll
        for (int u = 0; u < NB; u++) {
            int i = tid * 4 + u * THREADS * 4;
            int k = i / BN, nn = i % BN;
            *(float4*)&Bs[k][nn] = bR[u];
        }
        __syncthreads();

        // prefetch next tile (LDGs in flight during compute)
        if (t + 1 < nk) {
            int k0n = (t + 1) * BK;
            #pragma unroll
            for (int u = 0; u < NA; u++) {
                int i = tid * 4 + u * THREADS * 4;
                int m = i / BK, k = i % BK;
                aR[u] = (m0 + m < M) ? *(const float4*)&A[(m0 + m) * K + k0n + k]
                                     : make_float4(0.f, 0.f, 0.f, 0.f);
            }
            #pragma unroll
            for (int u = 0; u < NB; u++) {
                int i = tid * 4 + u * THREADS * 4;
                int k = i / BN, nn = i % BN;
                bR[u] = (n0 + nn < N) ? *(const float4*)&B[(k0n + k) * N + n0 + nn]
                                      : make_float4(0.f, 0.f, 0.f, 0.f);
            }
        }

        // compute current tile
        #pragma unroll
        for (int k = 0; k < BK; k++) {
            unsigned long long a2[TM];
            #pragma unroll
            for (int i = 0; i < TM; i++) a2[i] = As2[k][ty * TM + i];
            ulonglong2 bA = *(const ulonglong2*)&Bs[k][tx * 4];
            ulonglong2 bB = *(const ulonglong2*)&Bs[k][HALF + tx * 4];
            #pragma unroll
            for (int i = 0; i < TM; i++) {
                fma2(acc[i][0], a2[i], bA.x);
                fma2(acc[i][1], a2[i], bA.y);
                fma2(acc[i][2], a2[i], bB.x);
                fma2(acc[i][3], a2[i], bB.y);
            }
        }
        __syncthreads();
    }
    // epilogue
    #pragma unroll
    for (int i = 0; i < TM; i++) {
        int m = m0 + ty * TM + i;
        if (m >= M) continue;
        #pragma unroll
        for (int j = 0; j < 4; j++) {
            int nn = n0 + tx * 4 + 2 * (j & 1) + (j >> 1) * HALF;
            if (nn < N) {
                float lo, hi; upk2(acc[i][j], lo, hi);
                lo += bias[nn]; hi += bias[nn + 1];
                *(float2*)&Cout[m * N + nn] = make_float2(lo, hi);
            }
        }
    }
}

// ---------------- split-K partial GEMM: one BK=32 chunk per block ----------------
// BM=32, BN=64, 256 threads; grid (N/64, ceil(M/32), KSPLIT); K/KSPLIT == 32
__global__ __launch_bounds__(256) void gemm_splitk_kernel(
    const float* __restrict__ A, const float* __restrict__ B,
    float* __restrict__ part, int M, int N, int K)
{
    constexpr int BM = 32, BN = 64, BK = 32;
    constexpr int TX = 16, THREADS = 256;
    __shared__ unsigned long long As2[BK][BM];
    __shared__ float Bs[BK][BN];

    int tid = threadIdx.x;
    int tx = tid % TX, ty = tid / TX;
    int m0 = blockIdx.y * BM, n0 = blockIdx.x * BN;
    int z  = blockIdx.z;
    int k0 = z * BK;
    unsigned long long acc0[2] = {}, acc1[2] = {};

    for (int i = tid * 4; i < BM * BK; i += THREADS * 4) {
        int m = i / BK, k = i % BK;
        float4 v = make_float4(0.f, 0.f, 0.f, 0.f);
        if (m0 + m < M) v = *(const float4*)&A[(m0 + m) * K + k0 + k];
        As2[k + 0][m] = pk2(v.x, v.x);
        As2[k + 1][m] = pk2(v.y, v.y);
        As2[k + 2][m] = pk2(v.z, v.z);
        As2[k + 3][m] = pk2(v.w, v.w);
    }
    for (int i = tid * 4; i < BK * BN; i += THREADS * 4) {
        int k = i / BN, nn = i % BN;
        *(float4*)&Bs[k][nn] = *(const float4*)&B[(k0 + k) * N + n0 + nn];
    }
    __syncthreads();
    #pragma unroll
    for (int k = 0; k < BK; k++) {
        unsigned long long a0 = As2[k][ty * 2], a1 = As2[k][ty * 2 + 1];
        ulonglong2 bA = *(const ulonglong2*)&Bs[k][tx * 4];
        fma2(acc0[0], a0, bA.x);
        fma2(acc0[1], a0, bA.y);
        fma2(acc1[0], a1, bA.x);
        fma2(acc1[1], a1, bA.y);
    }
    float* dst = part + z * (N_ANCHOR * C_DIM);
    #pragma unroll
    for (int i = 0; i < 2; i++) {
        int m = m0 + ty * 2 + i;
        if (m >= M) continue;
        float4 v;
        unsigned long long* acc = i ? acc1 : acc0;
        upk2(acc[0], v.x, v.y);
        upk2(acc[1], v.z, v.w);
        *(float4*)&dst[m * N + n0 + tx * 4] = v;
    }
}

// reduce: out = inst + bias + sum_z part[z]   (float4 over 900*256 elems)
__global__ __launch_bounds__(256) void splitk_reduce_kernel(
    const float* __restrict__ inst, const float* __restrict__ bias,
    float* __restrict__ out)
{
    int idx = blockIdx.x * 256 + threadIdx.x;          // float4 index, 57600 total
    if (idx >= (N_ANCHOR * C_DIM) / 4) return;
    int nb = (idx & 63) * 4;                            // column base (C=256 -> 64 float4/row)
    float4 b = *(const float4*)&bias[nb];
    float4 r = ((const float4*)inst)[idx];
    float4 o;
    o.x = r.x + b.x; o.y = r.y + b.y; o.z = r.z + b.z; o.w = r.w + b.w;
    #pragma unroll
    for (int z = 0; z < KSPLIT; z++) {
        float4 s = ((const float4*)g_part)[idx + z * 57600];
        o.x += s.x; o.y += s.y; o.z += s.z; o.w += s.w;
    }
    ((float4*)out)[idx] = o;
}

// ---------------- kernel 3: fused softmax + deformable gather/aggregate ----------------
__global__ __launch_bounds__(320) void agg_kernel(const float* __restrict__ feature)
{
    int n = blockIdx.x, tid = threadIdx.x;           // 320 threads = 10 warps
    int lane = tid & 31, wid = tid >> 5;
    __shared__ float  w_s[NW];                        // logits -> softmax weights
    __shared__ float2 pts_s[NUM_CAMS * NUM_PTS];
    __shared__ uint2  entries[NCOMBO * 4];            // packed (combo<<17|row), bw
    __shared__ int    warpTot[10], warpBase[11];
    __shared__ float4 red4[5 * 64];                   // cross-slice reduction

    for (int i = tid; i < NW; i += 320) w_s[i] = g_W[n * NW + i];
    if (tid < NUM_CAMS * NUM_PTS) pts_s[tid] = g_pts[n * NUM_CAMS * NUM_PTS + tid];
    __syncthreads();

    // fused softmax over 312 combos: warp g handles group g
    if (wid < 8) {
        int g = wid;
        float v[10]; int cnt = 0; float mx = -1e30f;
        for (int i = lane; i < NCOMBO; i += 32) { float x = w_s[i * 8 + g]; v[cnt++] = x; mx = fmaxf(mx, x); }
        #pragma unroll
        for (int d = 16; d; d >>= 1) mx = fmaxf(mx, __shfl_xor_sync(0xffffffffu, mx, d));
        float sum = 0.f;
        for (int j = 0; j < cnt; j++) { v[j] = __expf(v[j] - mx); sum += v[j]; }
        #pragma unroll
        for (int d = 16; d; d >>= 1) sum += __shfl_xor_sync(0xffffffffu, sum, d);
        float inv = 1.0f / sum;
        cnt = 0;
        for (int i = lane; i < NCOMBO; i += 32) w_s[i * 8 + g] = v[cnt++] * inv;
    }

    // phase 1: each thread = one (cam,lvl,pt) combo; collect valid corners
    int myCnt = 0;
    uint32_t pk[4]; float bws[4];
    if (tid < NCOMBO) {
        int cam = tid / (NUM_LEVELS * NUM_PTS);
        int r   = tid % (NUM_LEVELS * NUM_PTS);
        int lvl = r / NUM_PTS, p = r % NUM_PTS;
        float2 pt = pts_s[cam * NUM_PTS + p];
        int Wl = c_lvlW[lvl], Hl = c_lvlH[lvl], st = c_start[lvl];
        float x = pt.x * (float)Wl - 0.5f;
        float y = pt.y * (float)Hl - 0.5f;
        float xf = floorf(x), yf = floorf(y);
        int x0 = (int)xf, y0 = (int)yf;
        float fx = x - xf, fy = y - yf;
        #pragma unroll
        for (int j = 0; j < 4; j++) {
            int xi = x0 + (j & 1), yi = y0 + (j >> 1);
            float bw = ((j & 1) ? fx : 1.f - fx) * ((j & 2) ? fy : 1.f - fy);
            if (xi >= 0 && xi < Wl && yi >= 0 && yi < Hl && bw > 0.f) {
                int rowIdx = cam * SUM_HW + st + yi * Wl + xi;
                pk[myCnt]  = ((uint32_t)tid << 17) | (uint32_t)rowIdx;
                bws[myCnt] = bw;
                myCnt++;
            }
        }
    }

    // deterministic compaction: warp shfl scan + cross-warp scan
    int incl = myCnt;
    #pragma unroll
    for (int d = 1; d < 32; d <<= 1) {
        int v = __shfl_up_sync(0xffffffffu, incl, d);
        if (lane >= d) incl += v;
    }
    if (lane == 31) warpTot[wid] = incl;
    __syncthreads();
    if (tid < 32) {
        int v = (tid < 10) ? warpTot[tid] : 0;
        int inc2 = v;
        #pragma unroll
        for (int d = 1; d < 32; d <<= 1) {
            int u = __shfl_up_sync(0xffffffffu, inc2, d);
            if (lane >= d) inc2 += u;
        }
        if (tid < 10) warpBase[tid] = inc2 - v;
        if (tid == 9) warpBase[10] = inc2;   // total entry count
    }
    __syncthreads();
    int base = warpBase[wid] + incl - myCnt;
    for (int j = 0; j < myCnt; j++)
        entries[base + j] = make_uint2(pk[j], __float_as_uint(bws[j]));
    __syncthreads();

    // phase 2: 64 channel-slots (16B each) x 5 entry slices, f32x2 accumulate
    int nE = warpBase[10];
    int cslot = tid & 63;                       // channel base = cslot*4
    int s = tid >> 6;                           // slice 0..4 (warp-uniform)
    int g = cslot >> 3;                         // group
    const ulonglong2* fb = (const ulonglong2*)feature + cslot;
    unsigned long long a0 = 0ull, a1 = 0ull;
    #pragma unroll 2
    for (int i = s; i < nE; i += 5) {
        uint2 e = entries[i];
        uint32_t rowIdx = e.x & 0x1FFFFu;
        float wv = __uint_as_float(e.y) * w_s[(e.x >> 17) * 8 + g];
        unsigned long long wv2 = pk2(wv, wv);
        ulonglong2 f = __ldg(&fb[rowIdx * 64u]);
        fma2(a0, wv2, f.x);
        fma2(a1, wv2, f.y);
    }
    {
        float4 accv;
        upk2(a0, accv.x, accv.y);
        upk2(a1, accv.z, accv.w);
        red4[s * 64 + cslot] = accv;
    }
    __syncthreads();
    if (tid < 256) {
        const float* rf = (const float*)red4;
        float sum = rf[tid] + rf[256 + tid] + rf[512 + tid] + rf[768 + tid] + rf[1024 + tid];
        g_agg[n * 256 + tid] = sum;
    }
}

// ---------------- launch ----------------
extern "C" void kernel_launch(void* const* d_in, const int* in_sizes, int n_in,
                              void* d_out, int out_size)
{
    const float* inst     = (const float*)d_in[0];
    const float* anchor   = (const float*)d_in[1];
    // d_in[2] time_interval unused
    const float* feature  = (const float*)d_in[3];
    // d_in[4] spatial_shapes, d_in[5] level_start_index: hardcoded constants
    const float* l2i      = (const float*)d_in[6];
    const float* img_wh   = (const float*)d_in[7];
    const float* enc_w    = (const float*)d_in[8];
    const float* enc_b    = (const float*)d_in[9];
    const float* kp_fixed = (const float*)d_in[10];
    const float* kp_w     = (const float*)d_in[11];
    const float* kp_b     = (const float*)d_in[12];
    const float* wfc_w    = (const float*)d_in[13];
    const float* wfc_b    = (const float*)d_in[14];
    const float* out_w    = (const float*)d_in[15];
    const float* out_b    = (const float*)d_in[16];
    float* out = (float*)d_out;

    float *pX, *pW, *pAgg, *pPart;
    cudaGetSymbolAddress((void**)&pX, g_X);
    cudaGetSymbolAddress((void**)&pW, g_W);
    cudaGetSymbolAddress((void**)&pAgg, g_agg);
    cudaGetSymbolAddress((void**)&pPart, g_part);

    precompute_kernel<<<N_ANCHOR, 128>>>(inst, anchor, l2i, img_wh,
                                         enc_w, enc_b, kp_fixed, kp_w, kp_b);
    // logits = X @ wfc_w + wfc_b : (900 x 2496), K=256 — double-buffered
    gemm_db_kernel<64, 128, 32, 4><<<dim3(20, 15), 256>>>(
        pX, wfc_w, wfc_b, pW, N_ANCHOR, NW, C_DIM);
    agg_kernel<<<N_ANCHOR, 320>>>(feature);
    // out = inst + agg @ out_w + out_b : split-K=8 partials + reduce
    gemm_splitk_kernel<<<dim3(4, 29, KSPLIT), 256>>>(
        pAgg, out_w, pPart, N_ANCHOR, C_DIM, C_DIM);
    splitk_reduce_kernel<<<225, 256>>>(inst, out_b, out);
}